// round 6
// baseline (speedup 1.0000x reference)
#include <cuda_runtime.h>
#include <cuda_bf16.h>
#include <cstdint>

#define BATCH 32768
#define HDIM  1024
#define NFAM  10

// quantization: v ~ s*(Q0 + Q1/254), clip at 5.5 sigma
#define SF_INV   (127.0f / 5.5f)                      // features (sigma 1)
#define SW1_INV  (127.0f * 45.25483400f / 5.5f)       // W1 (sigma 1/sqrt(2048))
#define SW2_INV  (127.0f * 32.0f / 5.5f)              // W2 (sigma 1/sqrt(1024))
#define SH_INV   (127.0f / 5.5f)                      // hidden (sigma ~1, relu>=0)
#define ESC1     ((5.5f/127.0f) * (5.5f/(127.0f*45.25483400f)) / 254.0f)
#define ESC2     ((5.5f/127.0f) * (5.5f/(127.0f*32.0f)) / 254.0f)

// ---------------------------------------------------------------- scratch
__device__ __align__(16) int     g_nearest[BATCH];
__device__ __align__(16) float   g_protoW1[NFAM * HDIM];
__device__ __align__(16) float   g_pp[NFAM];
__device__ __align__(16) int8_t  g_featq0[(size_t)BATCH * HDIM];
__device__ __align__(16) int8_t  g_featq1[(size_t)BATCH * HDIM];
__device__ __align__(16) int8_t  g_hidq0[(size_t)BATCH * HDIM];
__device__ __align__(16) int8_t  g_hidq1[(size_t)BATCH * HDIM];
__device__ __align__(16) int8_t  g_w1q0[HDIM * HDIM];
__device__ __align__(16) int8_t  g_w1q1[HDIM * HDIM];
__device__ __align__(16) int8_t  g_w2q0[HDIM * HDIM];
__device__ __align__(16) int8_t  g_w2q1[HDIM * HDIM];

// ---------------------------------------------------------------- helpers
__device__ __forceinline__ uint32_t smem_u32(const void* p) {
    uint32_t a;
    asm("{ .reg .u64 t; cvta.to.shared.u64 t, %1; cvt.u32.u64 %0, t; }" : "=r"(a) : "l"(p));
    return a;
}
__device__ __forceinline__ void cp16(uint32_t dst, const void* src) {
    asm volatile("cp.async.cg.shared.global [%0], [%1], 16;" :: "r"(dst), "l"(src) : "memory");
}
#define CP_COMMIT() asm volatile("cp.async.commit_group;" ::: "memory")
#define CP_WAIT1()  asm volatile("cp.async.wait_group 1;"  ::: "memory")

__device__ __forceinline__ void ldsm4(uint32_t& r0, uint32_t& r1, uint32_t& r2, uint32_t& r3,
                                      uint32_t addr) {
    asm volatile("ldmatrix.sync.aligned.m8n8.x4.shared.b16 {%0,%1,%2,%3}, [%4];"
                 : "=r"(r0), "=r"(r1), "=r"(r2), "=r"(r3) : "r"(addr));
}
__device__ __forceinline__ void imma16832(int* c, uint32_t a0, uint32_t a1, uint32_t a2,
                                          uint32_t a3, uint32_t b0, uint32_t b1) {
    asm volatile("mma.sync.aligned.m16n8k32.row.col.s32.s8.s8.s32 "
                 "{%0,%1,%2,%3}, {%4,%5,%6,%7}, {%8,%9}, {%0,%1,%2,%3};"
                 : "+r"(c[0]), "+r"(c[1]), "+r"(c[2]), "+r"(c[3])
                 : "r"(a0), "r"(a1), "r"(a2), "r"(a3), "r"(b0), "r"(b1));
}

// v ~ (1/inv) * (q0 + q1/254)
__device__ __forceinline__ void quant2(float v, float inv, int& q0, int& q1) {
    float x = fminf(fmaxf(v * inv, -127.f), 127.f);
    q0 = __float2int_rn(x);
    int r = __float2int_rn((x - (float)q0) * 254.f);
    q1 = max(-127, min(127, r));
}
__device__ __forceinline__ uint32_t pack4(int a, int b, int c, int d) {
    return (uint32_t)(a & 0xFF) | ((uint32_t)(b & 0xFF) << 8) |
           ((uint32_t)(c & 0xFF) << 16) | ((uint32_t)(d & 0xFF) << 24);
}

// ---------------------------------------------------------------- prep kernels
__global__ void pp_kernel(const float* __restrict__ protos) {
    const int j = threadIdx.x >> 5, lane = threadIdx.x & 31;
    if (j < NFAM) {
        float s = 0.f;
        for (int h = lane; h < HDIM; h += 32) {
            const float p = protos[j * HDIM + h];
            s = fmaf(p, p, s);
        }
#pragma unroll
        for (int o = 16; o > 0; o >>= 1) s += __shfl_xor_sync(0xffffffffu, s, o);
        if (lane == 0) g_pp[j] = s;
    }
}

// Fused: quantize features to int8 planes AND compute nearest prototype.
__global__ __launch_bounds__(256) void argquant_kernel(const float* __restrict__ feat,
                                                       const float* __restrict__ protos) {
    __shared__ float4 sp4[NFAM * 256];   // 40 KB
    for (int i = threadIdx.x; i < NFAM * 256; i += 256)
        sp4[i] = reinterpret_cast<const float4*>(protos)[i];
    __syncthreads();

    const int warp = threadIdx.x >> 5, lane = threadIdx.x & 31;
    const int row0 = (blockIdx.x * 8 + warp) * 4;

    float dot[NFAM][4];
#pragma unroll
    for (int j = 0; j < NFAM; ++j)
#pragma unroll
        for (int r = 0; r < 4; ++r) dot[j][r] = 0.f;

    for (int t = 0; t < 8; ++t) {
        const int idx = lane + 32 * t;       // float4 index within row
        float4 fv[4];
#pragma unroll
        for (int r = 0; r < 4; ++r)
            fv[r] = reinterpret_cast<const float4*>(feat)[(size_t)(row0 + r) * 256 + idx];

#pragma unroll
        for (int r = 0; r < 4; ++r) {
            int a0, a1, b0, b1, c0, c1, d0, d1;
            quant2(fv[r].x, SF_INV, a0, a1);
            quant2(fv[r].y, SF_INV, b0, b1);
            quant2(fv[r].z, SF_INV, c0, c1);
            quant2(fv[r].w, SF_INV, d0, d1);
            const size_t off = (size_t)(row0 + r) * 256 + idx;   // uint32 index (4 s8)
            reinterpret_cast<uint32_t*>(g_featq0)[off] = pack4(a0, b0, c0, d0);
            reinterpret_cast<uint32_t*>(g_featq1)[off] = pack4(a1, b1, c1, d1);
        }
#pragma unroll
        for (int j = 0; j < NFAM; ++j) {
            const float4 p = sp4[j * 256 + idx];
#pragma unroll
            for (int r = 0; r < 4; ++r) {
                float d = dot[j][r];
                d = fmaf(p.x, fv[r].x, d);
                d = fmaf(p.y, fv[r].y, d);
                d = fmaf(p.z, fv[r].z, d);
                d = fmaf(p.w, fv[r].w, d);
                dot[j][r] = d;
            }
        }
    }
#pragma unroll
    for (int j = 0; j < NFAM; ++j)
#pragma unroll
        for (int r = 0; r < 4; ++r)
#pragma unroll
            for (int o = 16; o > 0; o >>= 1)
                dot[j][r] += __shfl_xor_sync(0xffffffffu, dot[j][r], o);

    if (lane < 4) {
        const int r = lane;
        float best = g_pp[0] - 2.f * dot[0][r];
        int bi = 0;
#pragma unroll
        for (int j = 1; j < NFAM; ++j) {
            const float d = g_pp[j] - 2.f * dot[j][r];
            if (d < best) { best = d; bi = j; }
        }
        g_nearest[row0 + r] = bi;
    }
}

// transpose + quantize: dst[n*1024+k] = quant(W[k*1024+n]).  WHICH 0 -> w1q, 1 -> w2q.
template <int WHICH>
__global__ __launch_bounds__(256) void tquant_kernel(const float* __restrict__ W) {
    int8_t* q0p = (WHICH == 0) ? g_w1q0 : g_w2q0;
    int8_t* q1p = (WHICH == 0) ? g_w1q1 : g_w2q1;
    const float inv = (WHICH == 0) ? SW1_INV : SW2_INV;
    __shared__ float t[32][33];
    const int bx = blockIdx.x * 32, by = blockIdx.y * 32;
    const int tx = threadIdx.x, ty = threadIdx.y;   // (32, 8)
#pragma unroll
    for (int j = 0; j < 4; ++j)
        t[ty + 8 * j][tx] = W[(size_t)(by + ty + 8 * j) * HDIM + bx + tx];
    __syncthreads();
#pragma unroll
    for (int j = 0; j < 4; ++j) {
        int q0, q1;
        quant2(t[tx][ty + 8 * j], inv, q0, q1);
        q0p[(size_t)(bx + ty + 8 * j) * HDIM + by + tx] = (int8_t)q0;
        q1p[(size_t)(bx + ty + 8 * j) * HDIM + by + tx] = (int8_t)q1;
    }
}

// protoW1[j][n] = b1[n] + protos[j] . W1[H + :, n]   (exact fp32)
__global__ __launch_bounds__(256) void protow1_kernel(const float* __restrict__ protos,
                                                      const float* __restrict__ W1,
                                                      const float* __restrict__ b1) {
    const int n = blockIdx.x * 256 + threadIdx.x;
    const int j = blockIdx.y;
    const float* p = protos + j * HDIM;
    const float* w = W1 + (size_t)HDIM * HDIM + n;
    float acc = b1[n];
#pragma unroll 8
    for (int h = 0; h < HDIM; ++h) acc = fmaf(p[h], w[(size_t)h * HDIM], acc);
    g_protoW1[j * HDIM + n] = acc;
}

// ---------------------------------------------------------------- IMMA GEMM
// C[128x128 tile]: int8 2x7bit decomposition, 3 segments: A0B0, A0B1, A1B0.
// acc_final = 254*S00 + S01 + S10  (exact int32; fold by *254 after segment 0)
// K per segment = 1024 s8; slice = 64 s8 (64 bytes); 16 slices/segment, 48 total.
#define ROWB   80                      // 64 data bytes + 16 pad
#define ASTAGE (128 * ROWB)            // 10240
#define STAGEB (2 * ASTAGE)            // A + B
#define NSTG   3
#define GSMEM  (NSTG * STAGEB)         // 61440

template <bool FUSE1>
__global__ __launch_bounds__(256, 2) void imma_gemm_kernel(const float* __restrict__ b2,
                                                           float* __restrict__ out) {
    const int8_t* __restrict__ A0 = FUSE1 ? g_featq0 : g_hidq0;
    const int8_t* __restrict__ A1 = FUSE1 ? g_featq1 : g_hidq1;
    const int8_t* __restrict__ B0 = FUSE1 ? g_w1q0 : g_w2q0;
    const int8_t* __restrict__ B1 = FUSE1 ? g_w1q1 : g_w2q1;

    extern __shared__ char sm[];
    const uint32_t smA = smem_u32(sm);
    const uint32_t smB = smA + NSTG * ASTAGE;

    const int tid  = threadIdx.x;
    const int lane = tid & 31;
    const int wid  = tid >> 5;
    const int wm   = (wid & 3) * 32;     // warp M offset
    const int wn   = (wid >> 2) * 64;    // warp N offset
    const int bm   = blockIdx.y * 128;
    const int bn   = blockIdx.x * 128;

    // loader: 512 A-chunks + 512 B-chunks of 16B per stage; 2+2 per thread
    const int rA0 = tid >> 1,           kA0 = tid & 1;            // rows 0..127, k 0/1
    const int rA1 = tid >> 1,           kA1 = (tid & 1) + 2;      // k 2/3

    auto load_stage = [&](int s, int buf) {
        const int seg = s >> 4;
        const int8_t* gA = (seg == 2) ? A1 : A0;
        const int8_t* gB = (seg == 1) ? B1 : B0;
        const int kc = (s & 15) * 64;
        const uint32_t dA = smA + buf * ASTAGE;
        const uint32_t dB = smB + buf * ASTAGE;
        cp16(dA + rA0 * ROWB + kA0 * 16, gA + (size_t)(bm + rA0) * HDIM + kc + kA0 * 16);
        cp16(dA + rA1 * ROWB + kA1 * 16, gA + (size_t)(bm + rA1) * HDIM + kc + kA1 * 16);
        cp16(dB + rA0 * ROWB + kA0 * 16, gB + (size_t)(bn + rA0) * HDIM + kc + kA0 * 16);
        cp16(dB + rA1 * ROWB + kA1 * 16, gB + (size_t)(bn + rA1) * HDIM + kc + kA1 * 16);
    };

    int acc[2][8][4];
#pragma unroll
    for (int i = 0; i < 2; ++i)
#pragma unroll
        for (int j = 0; j < 8; ++j)
#pragma unroll
            for (int k = 0; k < 4; ++k) acc[i][j][k] = 0;

    const uint32_t aAddr0 = smA + (wm + (lane & 15)) * ROWB + (lane >> 4) * 16;
    const uint32_t bAddr0 = smB + (wn + (lane & 7) + ((lane >> 4) << 3)) * ROWB
                                + (((lane >> 3) & 1) << 4);

    load_stage(0, 0); CP_COMMIT();
    load_stage(1, 1); CP_COMMIT();

    for (int s = 0; s < 48; ++s) {
        CP_WAIT1();
        __syncthreads();
        if (s + 2 < 48) load_stage(s + 2, (s + 2) % NSTG);
        CP_COMMIT();

        const int buf = s % NSTG;
        const uint32_t aB = aAddr0 + buf * ASTAGE;
        const uint32_t bB = bAddr0 + buf * ASTAGE;
#pragma unroll
        for (int ks = 0; ks < 2; ++ks) {
            const int ko = ks * 32;
            uint32_t a[2][4];
#pragma unroll
            for (int mt = 0; mt < 2; ++mt)
                ldsm4(a[mt][0], a[mt][1], a[mt][2], a[mt][3], aB + mt * 16 * ROWB + ko);
            uint32_t b[4][4];
#pragma unroll
            for (int g = 0; g < 4; ++g)
                ldsm4(b[g][0], b[g][1], b[g][2], b[g][3], bB + g * 16 * ROWB + ko);
#pragma unroll
            for (int mt = 0; mt < 2; ++mt)
#pragma unroll
                for (int g = 0; g < 4; ++g) {
                    imma16832(acc[mt][g * 2 + 0], a[mt][0], a[mt][1], a[mt][2], a[mt][3],
                              b[g][0], b[g][1]);
                    imma16832(acc[mt][g * 2 + 1], a[mt][0], a[mt][1], a[mt][2], a[mt][3],
                              b[g][2], b[g][3]);
                }
        }
        if (s == 15) {   // fold: acc holds S00; weight it 254 vs S01+S10
#pragma unroll
            for (int i = 0; i < 2; ++i)
#pragma unroll
                for (int j = 0; j < 8; ++j)
#pragma unroll
                    for (int k = 0; k < 4; ++k) acc[i][j][k] *= 254;
        }
    }

    // ---------------- epilogue ----------------
    const float esc = FUSE1 ? ESC1 : ESC2;
    const int grp = lane >> 2;      // row within m8
    const int tig = lane & 3;       // col pair
#pragma unroll
    for (int mt = 0; mt < 2; ++mt) {
        const int r0 = bm + wm + mt * 16 + grp;
        const int r1 = r0 + 8;
        const float* av0;
        const float* av1;
        if (FUSE1) {
            av0 = g_protoW1 + (size_t)g_nearest[r0] * HDIM;
            av1 = g_protoW1 + (size_t)g_nearest[r1] * HDIM;
        } else {
            av0 = b2; av1 = b2;
        }
#pragma unroll
        for (int gg = 0; gg < 8; ++gg) {
            const int col = bn + wn + (gg >> 1) * 16 + (gg & 1) * 8 + tig * 2;
            const float2 p0 = *reinterpret_cast<const float2*>(av0 + col);
            const float2 p1 = *reinterpret_cast<const float2*>(av1 + col);
            float v00 = (float)acc[mt][gg][0] * esc + p0.x;
            float v01 = (float)acc[mt][gg][1] * esc + p0.y;
            float v10 = (float)acc[mt][gg][2] * esc + p1.x;
            float v11 = (float)acc[mt][gg][3] * esc + p1.y;
            if (FUSE1) {
                v00 = fmaxf(v00, 0.f); v01 = fmaxf(v01, 0.f);
                v10 = fmaxf(v10, 0.f); v11 = fmaxf(v11, 0.f);
                int q00a, q00b, q01a, q01b, q10a, q10b, q11a, q11b;
                quant2(v00, SH_INV, q00a, q00b);
                quant2(v01, SH_INV, q01a, q01b);
                quant2(v10, SH_INV, q10a, q10b);
                quant2(v11, SH_INV, q11a, q11b);
                *reinterpret_cast<unsigned short*>(g_hidq0 + (size_t)r0 * HDIM + col) =
                    (unsigned short)((q00a & 0xFF) | ((q01a & 0xFF) << 8));
                *reinterpret_cast<unsigned short*>(g_hidq1 + (size_t)r0 * HDIM + col) =
                    (unsigned short)((q00b & 0xFF) | ((q01b & 0xFF) << 8));
                *reinterpret_cast<unsigned short*>(g_hidq0 + (size_t)r1 * HDIM + col) =
                    (unsigned short)((q10a & 0xFF) | ((q11a & 0xFF) << 8));
                *reinterpret_cast<unsigned short*>(g_hidq1 + (size_t)r1 * HDIM + col) =
                    (unsigned short)((q10b & 0xFF) | ((q11b & 0xFF) << 8));
            } else {
                *reinterpret_cast<float2*>(out + (size_t)r0 * HDIM + col) = make_float2(v00, v01);
                *reinterpret_cast<float2*>(out + (size_t)r1 * HDIM + col) = make_float2(v10, v11);
            }
        }
    }
}

// ---------------------------------------------------------------- launch
extern "C" void kernel_launch(void* const* d_in, const int* in_sizes, int n_in,
                              void* d_out, int out_size) {
    (void)in_sizes; (void)n_in; (void)out_size;
    const float* features = (const float*)d_in[0];
    const float* protos   = (const float*)d_in[1];
    const float* W1       = (const float*)d_in[2];
    const float* b1       = (const float*)d_in[3];
    const float* W2       = (const float*)d_in[4];
    const float* b2       = (const float*)d_in[5];
    float* out = (float*)d_out;

    cudaFuncSetAttribute(imma_gemm_kernel<true>,  cudaFuncAttributeMaxDynamicSharedMemorySize, GSMEM);
    cudaFuncSetAttribute(imma_gemm_kernel<false>, cudaFuncAttributeMaxDynamicSharedMemorySize, GSMEM);

    pp_kernel<<<1, 320>>>(protos);
    argquant_kernel<<<BATCH / 32, 256>>>(features, protos);
    tquant_kernel<0><<<dim3(32, 32), dim3(32, 8)>>>(W1);
    tquant_kernel<1><<<dim3(32, 32), dim3(32, 8)>>>(W2);
    protow1_kernel<<<dim3(HDIM / 256, NFAM), 256>>>(protos, W1, b1);

    dim3 grid(HDIM / 128, BATCH / 128);   // (8, 256)
    imma_gemm_kernel<true><<<grid, 256, GSMEM>>>(nullptr, nullptr);
    imma_gemm_kernel<false><<<grid, 256, GSMEM>>>(b2, out);
}

// round 8
// speedup vs baseline: 2.4059x; 2.4059x over previous
#include <cuda_runtime.h>
#include <cuda_bf16.h>
#include <cstdint>

#define BATCH 32768
#define HDIM  1024
#define NFAM  10

// ---------------------------------------------------------------- scratch
__device__ __align__(16) int       g_nearest[BATCH];
__device__ __align__(16) float     g_protoW1[NFAM * HDIM];
__device__ __align__(16) float     g_pp[NFAM];
__device__ __align__(16) uint32_t  g_feat[(size_t)BATCH * HDIM];   // tf32 bits
__device__ __align__(16) uint32_t  g_hid[(size_t)BATCH * HDIM];    // tf32 bits
__device__ __align__(16) uint32_t  g_w1t[HDIM * HDIM];             // tf32 bits, transposed
__device__ __align__(16) uint32_t  g_w2t[HDIM * HDIM];             // tf32 bits, transposed

// ---------------------------------------------------------------- helpers
__device__ __forceinline__ uint32_t smem_u32(const void* p) {
    uint32_t a;
    asm("{ .reg .u64 t; cvta.to.shared.u64 t, %1; cvt.u32.u64 %0, t; }" : "=r"(a) : "l"(p));
    return a;
}
__device__ __forceinline__ void cp16(uint32_t dst, const void* src) {
    asm volatile("cp.async.cg.shared.global [%0], [%1], 16;" :: "r"(dst), "l"(src) : "memory");
}
#define CP_COMMIT() asm volatile("cp.async.commit_group;" ::: "memory")
#define CP_WAIT1()  asm volatile("cp.async.wait_group 1;"  ::: "memory")

__device__ __forceinline__ void ldsm4(uint32_t& r0, uint32_t& r1, uint32_t& r2, uint32_t& r3,
                                      uint32_t addr) {
    asm volatile("ldmatrix.sync.aligned.m8n8.x4.shared.b16 {%0,%1,%2,%3}, [%4];"
                 : "=r"(r0), "=r"(r1), "=r"(r2), "=r"(r3) : "r"(addr));
}
__device__ __forceinline__ void mma_tf32(float* c, uint32_t a0, uint32_t a1, uint32_t a2,
                                         uint32_t a3, uint32_t b0, uint32_t b1) {
    asm volatile("mma.sync.aligned.m16n8k8.row.col.f32.tf32.tf32.f32 "
                 "{%0,%1,%2,%3}, {%4,%5,%6,%7}, {%8,%9}, {%0,%1,%2,%3};"
                 : "+f"(c[0]), "+f"(c[1]), "+f"(c[2]), "+f"(c[3])
                 : "r"(a0), "r"(a1), "r"(a2), "r"(a3), "r"(b0), "r"(b1));
}
__device__ __forceinline__ uint32_t f2tf32(float v) {
    uint32_t r;
    asm("cvt.rna.tf32.f32 %0, %1;" : "=r"(r) : "f"(v));
    return r;
}

// ---------------------------------------------------------------- prep kernels
__global__ void pp_kernel(const float* __restrict__ protos) {
    const int j = threadIdx.x >> 5, lane = threadIdx.x & 31;
    if (j < NFAM) {
        float s = 0.f;
        for (int h = lane; h < HDIM; h += 32) {
            const float p = protos[j * HDIM + h];
            s = fmaf(p, p, s);
        }
#pragma unroll
        for (int o = 16; o > 0; o >>= 1) s += __shfl_xor_sync(0xffffffffu, s, o);
        if (lane == 0) g_pp[j] = s;
    }
}

// Fused: convert features to tf32 AND compute nearest prototype.
__global__ __launch_bounds__(256) void argcvt_kernel(const float* __restrict__ feat,
                                                     const float* __restrict__ protos) {
    __shared__ float4 sp4[NFAM * 256];   // 40 KB
    for (int i = threadIdx.x; i < NFAM * 256; i += 256)
        sp4[i] = reinterpret_cast<const float4*>(protos)[i];
    __syncthreads();

    const int warp = threadIdx.x >> 5, lane = threadIdx.x & 31;
    const int row0 = (blockIdx.x * 8 + warp) * 4;

    float dot[NFAM][4];
#pragma unroll
    for (int j = 0; j < NFAM; ++j)
#pragma unroll
        for (int r = 0; r < 4; ++r) dot[j][r] = 0.f;

    for (int t = 0; t < 8; ++t) {
        const int idx = lane + 32 * t;       // float4 index within row
        float4 fv[4];
#pragma unroll
        for (int r = 0; r < 4; ++r)
            fv[r] = reinterpret_cast<const float4*>(feat)[(size_t)(row0 + r) * 256 + idx];

#pragma unroll
        for (int r = 0; r < 4; ++r) {
            uint4 tv;
            tv.x = f2tf32(fv[r].x); tv.y = f2tf32(fv[r].y);
            tv.z = f2tf32(fv[r].z); tv.w = f2tf32(fv[r].w);
            reinterpret_cast<uint4*>(g_feat)[(size_t)(row0 + r) * 256 + idx] = tv;
        }
#pragma unroll
        for (int j = 0; j < NFAM; ++j) {
            const float4 p = sp4[j * 256 + idx];
#pragma unroll
            for (int r = 0; r < 4; ++r) {
                float d = dot[j][r];
                d = fmaf(p.x, fv[r].x, d);
                d = fmaf(p.y, fv[r].y, d);
                d = fmaf(p.z, fv[r].z, d);
                d = fmaf(p.w, fv[r].w, d);
                dot[j][r] = d;
            }
        }
    }
#pragma unroll
    for (int j = 0; j < NFAM; ++j)
#pragma unroll
        for (int r = 0; r < 4; ++r)
#pragma unroll
            for (int o = 16; o > 0; o >>= 1)
                dot[j][r] += __shfl_xor_sync(0xffffffffu, dot[j][r], o);

    if (lane < 4) {
        const int r = lane;
        float best = g_pp[0] - 2.f * dot[0][r];
        int bi = 0;
#pragma unroll
        for (int j = 1; j < NFAM; ++j) {
            const float d = g_pp[j] - 2.f * dot[j][r];
            if (d < best) { best = d; bi = j; }
        }
        g_nearest[row0 + r] = bi;
    }
}

// transpose + tf32 convert: dst[n*1024+k] = tf32(W[k*1024+n]).  WHICH 0 -> w1t, 1 -> w2t.
template <int WHICH>
__global__ __launch_bounds__(256) void tcvt_kernel(const float* __restrict__ W) {
    uint32_t* dst = (WHICH == 0) ? g_w1t : g_w2t;
    __shared__ float t[32][33];
    const int bx = blockIdx.x * 32, by = blockIdx.y * 32;
    const int tx = threadIdx.x, ty = threadIdx.y;   // (32, 8)
#pragma unroll
    for (int j = 0; j < 4; ++j)
        t[ty + 8 * j][tx] = W[(size_t)(by + ty + 8 * j) * HDIM + bx + tx];
    __syncthreads();
#pragma unroll
    for (int j = 0; j < 4; ++j)
        dst[(size_t)(bx + ty + 8 * j) * HDIM + by + tx] = f2tf32(t[tx][ty + 8 * j]);
}

// protoW1[j][n] = b1[n] + protos[j] . W1[H + :, n]   (exact fp32)
__global__ __launch_bounds__(256) void protow1_kernel(const float* __restrict__ protos,
                                                      const float* __restrict__ W1,
                                                      const float* __restrict__ b1) {
    const int n = blockIdx.x * 256 + threadIdx.x;
    const int j = blockIdx.y;
    const float* p = protos + j * HDIM;
    const float* w = W1 + (size_t)HDIM * HDIM + n;
    float acc = b1[n];
#pragma unroll 8
    for (int h = 0; h < HDIM; ++h) acc = fmaf(p[h], w[(size_t)h * HDIM], acc);
    g_protoW1[j * HDIM + n] = acc;
}

// ---------------------------------------------------------------- TF32 GEMM
// Block tile 128x128, 8 warps 4(M)x2(N), warp tile 32x64.
// BK = 32 tf32 (128 B rows). K = 1024 -> 32 stages. m16n8k8 tf32 MMA.
#define ROWB   144                     // 128 data bytes + 16 pad
#define TSTAGE (128 * ROWB)            // 18432
#define STAGEB (2 * TSTAGE)            // A + B
#define NSTG   3
#define GSMEM  (NSTG * STAGEB)         // 110592

template <bool FUSE1>
__global__ __launch_bounds__(256, 2) void tf32_gemm_kernel(const float* __restrict__ b2,
                                                           float* __restrict__ out) {
    const uint32_t* __restrict__ A = FUSE1 ? g_feat : g_hid;
    const uint32_t* __restrict__ B = FUSE1 ? g_w1t : g_w2t;

    extern __shared__ char sm[];
    const uint32_t smA = smem_u32(sm);

    const int tid  = threadIdx.x;
    const int lane = tid & 31;
    const int wid  = tid >> 5;
    const int wm   = (wid & 3) * 32;     // warp M offset
    const int wn   = (wid >> 2) * 64;    // warp N offset
    const int bm   = blockIdx.y * 128;
    const int bn   = blockIdx.x * 128;

    // loader: 1024 A-chunks + 1024 B-chunks of 16B per stage; 4+4 per thread.
    // thread covers row tid>>1, k-pieces (tid&1)+2i, i=0..3 (full 8 pieces x 2 threads).
    const int lrow = tid >> 1;                 // 0..127
    const int lkb  = tid & 1;                  // base piece 0/1

    auto load_stage = [&](int s, int buf) {
        const int kc = s * 32;                 // tf32 offset of slice
        const uint32_t dA = smA + buf * STAGEB + lrow * ROWB;
        const uint32_t dB = dA + TSTAGE;
        const uint32_t* gA = A + (size_t)(bm + lrow) * HDIM + kc;
        const uint32_t* gB = B + (size_t)(bn + lrow) * HDIM + kc;
#pragma unroll
        for (int i = 0; i < 4; ++i) {
            const int k = lkb + 2 * i;         // 16B piece 0..7
            cp16(dA + k * 16, gA + k * 4);
            cp16(dB + k * 16, gB + k * 4);
        }
    };

    float acc[2][8][4];
#pragma unroll
    for (int i = 0; i < 2; ++i)
#pragma unroll
        for (int j = 0; j < 8; ++j)
#pragma unroll
            for (int k = 0; k < 4; ++k) acc[i][j][k] = 0.f;

    // A x4: [rows 0-7 k0-3 | rows 8-15 k0-3 | rows 0-7 k4-7 | rows 8-15 k4-7] per slice
    const uint32_t aAddr0 = smA + (wm + (lane & 15)) * ROWB + (lane >> 4) * 16;
    // B x4: [n 0-7 k0-3 | n 0-7 k4-7 | n 8-15 k0-3 | n 8-15 k4-7]
    const uint32_t bAddr0 = smA + TSTAGE + (wn + (lane & 7) + ((lane >> 4) << 3)) * ROWB
                                + (((lane >> 3) & 1) << 4);

    load_stage(0, 0); CP_COMMIT();
    load_stage(1, 1); CP_COMMIT();

    for (int s = 0; s < 32; ++s) {
        CP_WAIT1();
        __syncthreads();
        if (s + 2 < 32) load_stage(s + 2, (s + 2) % NSTG);
        CP_COMMIT();

        const int buf = s % NSTG;
        const uint32_t aB = aAddr0 + buf * STAGEB;
        const uint32_t bB = bAddr0 + buf * STAGEB;
#pragma unroll
        for (int ks = 0; ks < 4; ++ks) {           // 4 k-slices of 8 tf32 (32 B each)
            const int ko = ks * 32;
            uint32_t a[2][4];
#pragma unroll
            for (int mt = 0; mt < 2; ++mt)
                ldsm4(a[mt][0], a[mt][1], a[mt][2], a[mt][3], aB + mt * 16 * ROWB + ko);
            uint32_t b[4][4];
#pragma unroll
            for (int g = 0; g < 4; ++g)
                ldsm4(b[g][0], b[g][1], b[g][2], b[g][3], bB + g * 16 * ROWB + ko);
#pragma unroll
            for (int mt = 0; mt < 2; ++mt)
#pragma unroll
                for (int g = 0; g < 4; ++g) {
                    mma_tf32(acc[mt][g * 2 + 0], a[mt][0], a[mt][1], a[mt][2], a[mt][3],
                             b[g][0], b[g][1]);
                    mma_tf32(acc[mt][g * 2 + 1], a[mt][0], a[mt][1], a[mt][2], a[mt][3],
                             b[g][2], b[g][3]);
                }
        }
    }

    // ---------------- epilogue ----------------
    const int grp = lane >> 2;      // row within m8
    const int tig = lane & 3;       // col pair
#pragma unroll
    for (int mt = 0; mt < 2; ++mt) {
        const int r0 = bm + wm + mt * 16 + grp;
        const int r1 = r0 + 8;
        const float* av0;
        const float* av1;
        if (FUSE1) {
            av0 = g_protoW1 + (size_t)g_nearest[r0] * HDIM;
            av1 = g_protoW1 + (size_t)g_nearest[r1] * HDIM;
        } else {
            av0 = b2; av1 = b2;
        }
#pragma unroll
        for (int gg = 0; gg < 8; ++gg) {
            const int col = bn + wn + (gg >> 1) * 16 + (gg & 1) * 8 + tig * 2;
            const float2 p0 = *reinterpret_cast<const float2*>(av0 + col);
            const float2 p1 = *reinterpret_cast<const float2*>(av1 + col);
            float v00 = acc[mt][gg][0] + p0.x, v01 = acc[mt][gg][1] + p0.y;
            float v10 = acc[mt][gg][2] + p1.x, v11 = acc[mt][gg][3] + p1.y;
            if (FUSE1) {
                v00 = fmaxf(v00, 0.f); v01 = fmaxf(v01, 0.f);
                v10 = fmaxf(v10, 0.f); v11 = fmaxf(v11, 0.f);
                uint2 h0, h1;
                h0.x = f2tf32(v00); h0.y = f2tf32(v01);
                h1.x = f2tf32(v10); h1.y = f2tf32(v11);
                *reinterpret_cast<uint2*>(g_hid + (size_t)r0 * HDIM + col) = h0;
                *reinterpret_cast<uint2*>(g_hid + (size_t)r1 * HDIM + col) = h1;
            } else {
                *reinterpret_cast<float2*>(out + (size_t)r0 * HDIM + col) = make_float2(v00, v01);
                *reinterpret_cast<float2*>(out + (size_t)r1 * HDIM + col) = make_float2(v10, v11);
            }
        }
    }
}

// ---------------------------------------------------------------- launch
extern "C" void kernel_launch(void* const* d_in, const int* in_sizes, int n_in,
                              void* d_out, int out_size) {
    (void)in_sizes; (void)n_in; (void)out_size;
    const float* features = (const float*)d_in[0];
    const float* protos   = (const float*)d_in[1];
    const float* W1       = (const float*)d_in[2];
    const float* b1       = (const float*)d_in[3];
    const float* W2       = (const float*)d_in[4];
    const float* b2       = (const float*)d_in[5];
    float* out = (float*)d_out;

    cudaFuncSetAttribute(tf32_gemm_kernel<true>,  cudaFuncAttributeMaxDynamicSharedMemorySize, GSMEM);
    cudaFuncSetAttribute(tf32_gemm_kernel<false>, cudaFuncAttributeMaxDynamicSharedMemorySize, GSMEM);

    pp_kernel<<<1, 320>>>(protos);
    argcvt_kernel<<<BATCH / 32, 256>>>(features, protos);
    tcvt_kernel<0><<<dim3(32, 32), dim3(32, 8)>>>(W1);
    tcvt_kernel<1><<<dim3(32, 32), dim3(32, 8)>>>(W2);
    protow1_kernel<<<dim3(HDIM / 256, NFAM), 256>>>(protos, W1, b1);

    dim3 grid(HDIM / 128, BATCH / 128);   // (8, 256)
    tf32_gemm_kernel<true><<<grid, 256, GSMEM>>>(nullptr, nullptr);
    tf32_gemm_kernel<false><<<grid, 256, GSMEM>>>(b2, out);
}

// round 9
// speedup vs baseline: 5.5295x; 2.2984x over previous
#include <cuda_runtime.h>
#include <cuda_fp16.h>
#include <cstdint>

#define BATCH 32768
#define HDIM  1024
#define NFAM  10

// ---------------------------------------------------------------- scratch
__device__ __align__(16) int     g_nearest[BATCH];
__device__ __align__(16) float   g_protoW1[NFAM * HDIM];
__device__ __align__(16) float   g_pp[NFAM];
__device__ __align__(16) __half  g_feat[(size_t)BATCH * HDIM];
__device__ __align__(16) __half  g_hid[(size_t)BATCH * HDIM];
__device__ __align__(16) __half  g_w1t[HDIM * HDIM];    // transposed
__device__ __align__(16) __half  g_w2t[HDIM * HDIM];    // transposed

// ---------------------------------------------------------------- helpers
__device__ __forceinline__ uint32_t smem_u32(const void* p) {
    uint32_t a;
    asm("{ .reg .u64 t; cvta.to.shared.u64 t, %1; cvt.u32.u64 %0, t; }" : "=r"(a) : "l"(p));
    return a;
}
__device__ __forceinline__ void cp16(uint32_t dst, const void* src) {
    asm volatile("cp.async.cg.shared.global [%0], [%1], 16;" :: "r"(dst), "l"(src) : "memory");
}
#define CP_COMMIT() asm volatile("cp.async.commit_group;" ::: "memory")
#define CP_WAIT1()  asm volatile("cp.async.wait_group 1;"  ::: "memory")

__device__ __forceinline__ void ldsm4(uint32_t& r0, uint32_t& r1, uint32_t& r2, uint32_t& r3,
                                      uint32_t addr) {
    asm volatile("ldmatrix.sync.aligned.m8n8.x4.shared.b16 {%0,%1,%2,%3}, [%4];"
                 : "=r"(r0), "=r"(r1), "=r"(r2), "=r"(r3) : "r"(addr));
}
__device__ __forceinline__ void mma_f16(float* c, uint32_t a0, uint32_t a1, uint32_t a2,
                                        uint32_t a3, uint32_t b0, uint32_t b1) {
    asm volatile("mma.sync.aligned.m16n8k16.row.col.f32.f16.f16.f32 "
                 "{%0,%1,%2,%3}, {%4,%5,%6,%7}, {%8,%9}, {%0,%1,%2,%3};"
                 : "+f"(c[0]), "+f"(c[1]), "+f"(c[2]), "+f"(c[3])
                 : "r"(a0), "r"(a1), "r"(a2), "r"(a3), "r"(b0), "r"(b1));
}

// ---------------------------------------------------------------- prep kernels
__global__ void pp_kernel(const float* __restrict__ protos) {
    const int j = threadIdx.x >> 5, lane = threadIdx.x & 31;
    if (j < NFAM) {
        float s = 0.f;
        for (int h = lane; h < HDIM; h += 32) {
            const float p = protos[j * HDIM + h];
            s = fmaf(p, p, s);
        }
#pragma unroll
        for (int o = 16; o > 0; o >>= 1) s += __shfl_xor_sync(0xffffffffu, s, o);
        if (lane == 0) g_pp[j] = s;
    }
}

// Fused: convert features to fp16 AND compute nearest prototype.
__global__ __launch_bounds__(256) void argcvt_kernel(const float* __restrict__ feat,
                                                     const float* __restrict__ protos) {
    __shared__ float4 sp4[NFAM * 256];   // 40 KB
    for (int i = threadIdx.x; i < NFAM * 256; i += 256)
        sp4[i] = reinterpret_cast<const float4*>(protos)[i];
    __syncthreads();

    const int warp = threadIdx.x >> 5, lane = threadIdx.x & 31;
    const int row0 = (blockIdx.x * 8 + warp) * 4;

    float dot[NFAM][4];
#pragma unroll
    for (int j = 0; j < NFAM; ++j)
#pragma unroll
        for (int r = 0; r < 4; ++r) dot[j][r] = 0.f;

    for (int t = 0; t < 8; ++t) {
        const int idx = lane + 32 * t;       // float4 index within row
        float4 fv[4];
#pragma unroll
        for (int r = 0; r < 4; ++r)
            fv[r] = reinterpret_cast<const float4*>(feat)[(size_t)(row0 + r) * 256 + idx];

#pragma unroll
        for (int r = 0; r < 4; ++r) {
            __half2 h0 = __floats2half2_rn(fv[r].x, fv[r].y);
            __half2 h1 = __floats2half2_rn(fv[r].z, fv[r].w);
            uint2 pkt;
            pkt.x = *reinterpret_cast<uint32_t*>(&h0);
            pkt.y = *reinterpret_cast<uint32_t*>(&h1);
            reinterpret_cast<uint2*>(g_feat)[(size_t)(row0 + r) * 256 + idx] = pkt;
        }
#pragma unroll
        for (int j = 0; j < NFAM; ++j) {
            const float4 p = sp4[j * 256 + idx];
#pragma unroll
            for (int r = 0; r < 4; ++r) {
                float d = dot[j][r];
                d = fmaf(p.x, fv[r].x, d);
                d = fmaf(p.y, fv[r].y, d);
                d = fmaf(p.z, fv[r].z, d);
                d = fmaf(p.w, fv[r].w, d);
                dot[j][r] = d;
            }
        }
    }
#pragma unroll
    for (int j = 0; j < NFAM; ++j)
#pragma unroll
        for (int r = 0; r < 4; ++r)
#pragma unroll
            for (int o = 16; o > 0; o >>= 1)
                dot[j][r] += __shfl_xor_sync(0xffffffffu, dot[j][r], o);

    if (lane < 4) {
        const int r = lane;
        float best = g_pp[0] - 2.f * dot[0][r];
        int bi = 0;
#pragma unroll
        for (int j = 1; j < NFAM; ++j) {
            const float d = g_pp[j] - 2.f * dot[j][r];
            if (d < best) { best = d; bi = j; }
        }
        g_nearest[row0 + r] = bi;
    }
}

// transpose + fp16 convert: dst[n*1024+k] = half(W[k*1024+n]).  WHICH 0 -> w1t, 1 -> w2t.
template <int WHICH>
__global__ __launch_bounds__(256) void tcvt_kernel(const float* __restrict__ W) {
    __half* dst = (WHICH == 0) ? g_w1t : g_w2t;
    __shared__ float t[32][33];
    const int bx = blockIdx.x * 32, by = blockIdx.y * 32;
    const int tx = threadIdx.x, ty = threadIdx.y;   // (32, 8)
#pragma unroll
    for (int j = 0; j < 4; ++j)
        t[ty + 8 * j][tx] = W[(size_t)(by + ty + 8 * j) * HDIM + bx + tx];
    __syncthreads();
#pragma unroll
    for (int j = 0; j < 4; ++j)
        dst[(size_t)(bx + ty + 8 * j) * HDIM + by + tx] = __float2half_rn(t[tx][ty + 8 * j]);
}

// protoW1[j][n] = b1[n] + protos[j] . W1[H + :, n]   (exact fp32)
__global__ __launch_bounds__(256) void protow1_kernel(const float* __restrict__ protos,
                                                      const float* __restrict__ W1,
                                                      const float* __restrict__ b1) {
    const int n = blockIdx.x * 256 + threadIdx.x;
    const int j = blockIdx.y;
    const float* p = protos + j * HDIM;
    const float* w = W1 + (size_t)HDIM * HDIM + n;
    float acc = b1[n];
#pragma unroll 8
    for (int h = 0; h < HDIM; ++h) acc = fmaf(p[h], w[(size_t)h * HDIM], acc);
    g_protoW1[j * HDIM + n] = acc;
}

// ---------------------------------------------------------------- FP16 GEMM
// Block tile 128x128, 8 warps 4(M)x2(N), warp tile 32x64.
// BK = 32 halves (64 B rows). K = 1024 -> 32 stages. m16n8k16 fp16 MMA, fp32 acc.
#define ROWB   80                      // 64 data bytes + 16 pad
#define TSTAGE (128 * ROWB)            // 10240
#define STAGEB (2 * TSTAGE)            // A + B
#define NSTG   3
#define GSMEM  (NSTG * STAGEB)         // 61440

template <bool FUSE1>
__global__ __launch_bounds__(256, 2) void f16_gemm_kernel(const float* __restrict__ b2,
                                                          float* __restrict__ out) {
    const __half* __restrict__ A = FUSE1 ? g_feat : g_hid;
    const __half* __restrict__ B = FUSE1 ? g_w1t : g_w2t;

    extern __shared__ char sm[];
    const uint32_t smA = smem_u32(sm);

    const int tid  = threadIdx.x;
    const int lane = tid & 31;
    const int wid  = tid >> 5;
    const int wm   = (wid & 3) * 32;     // warp M offset
    const int wn   = (wid >> 2) * 64;    // warp N offset
    const int bm   = blockIdx.y * 128;
    const int bn   = blockIdx.x * 128;

    // loader: 512 A-chunks + 512 B-chunks of 16B per stage; 2+2 per thread.
    const int rA0 = tid >> 2,         kA0 = tid & 3;          // chunk tid
    const int rA1 = (tid + 256) >> 2, kA1 = (tid + 256) & 3;  // chunk tid+256

    auto load_stage = [&](int s, int buf) {
        const int kc = s * 32;               // half offset
        const uint32_t dA = smA + buf * STAGEB;
        const uint32_t dB = dA + TSTAGE;
        cp16(dA + rA0 * ROWB + kA0 * 16, A + (size_t)(bm + rA0) * HDIM + kc + kA0 * 8);
        cp16(dA + rA1 * ROWB + kA1 * 16, A + (size_t)(bm + rA1) * HDIM + kc + kA1 * 8);
        cp16(dB + rA0 * ROWB + kA0 * 16, B + (size_t)(bn + rA0) * HDIM + kc + kA0 * 8);
        cp16(dB + rA1 * ROWB + kA1 * 16, B + (size_t)(bn + rA1) * HDIM + kc + kA1 * 8);
    };

    float acc[2][8][4];
#pragma unroll
    for (int i = 0; i < 2; ++i)
#pragma unroll
        for (int j = 0; j < 8; ++j)
#pragma unroll
            for (int k = 0; k < 4; ++k) acc[i][j][k] = 0.f;

    const uint32_t aAddr0 = smA + (wm + (lane & 15)) * ROWB + (lane >> 4) * 16;
    const uint32_t bAddr0 = smA + TSTAGE + (wn + (lane & 7) + ((lane >> 4) << 3)) * ROWB
                                + (((lane >> 3) & 1) << 4);

    load_stage(0, 0); CP_COMMIT();
    load_stage(1, 1); CP_COMMIT();

    for (int s = 0; s < 32; ++s) {
        CP_WAIT1();
        __syncthreads();
        if (s + 2 < 32) load_stage(s + 2, (s + 2) % NSTG);
        CP_COMMIT();

        const int buf = s % NSTG;
        const uint32_t aB = aAddr0 + buf * STAGEB;
        const uint32_t bB = bAddr0 + buf * STAGEB;
#pragma unroll
        for (int ks = 0; ks < 2; ++ks) {       // 2 k-slices of 16 halves (32 B each)
            const int ko = ks * 32;
            uint32_t a[2][4];
#pragma unroll
            for (int mt = 0; mt < 2; ++mt)
                ldsm4(a[mt][0], a[mt][1], a[mt][2], a[mt][3], aB + mt * 16 * ROWB + ko);
            uint32_t b[4][4];
#pragma unroll
            for (int g = 0; g < 4; ++g)
                ldsm4(b[g][0], b[g][1], b[g][2], b[g][3], bB + g * 16 * ROWB + ko);
#pragma unroll
            for (int mt = 0; mt < 2; ++mt)
#pragma unroll
                for (int g = 0; g < 4; ++g) {
                    mma_f16(acc[mt][g * 2 + 0], a[mt][0], a[mt][1], a[mt][2], a[mt][3],
                            b[g][0], b[g][1]);
                    mma_f16(acc[mt][g * 2 + 1], a[mt][0], a[mt][1], a[mt][2], a[mt][3],
                            b[g][2], b[g][3]);
                }
        }
    }

    // ---------------- epilogue ----------------
    const int grp = lane >> 2;      // row within m8
    const int tig = lane & 3;       // col pair
#pragma unroll
    for (int mt = 0; mt < 2; ++mt) {
        const int r0 = bm + wm + mt * 16 + grp;
        const int r1 = r0 + 8;
        const float* av0;
        const float* av1;
        if (FUSE1) {
            av0 = g_protoW1 + (size_t)g_nearest[r0] * HDIM;
            av1 = g_protoW1 + (size_t)g_nearest[r1] * HDIM;
        } else {
            av0 = b2; av1 = b2;
        }
#pragma unroll
        for (int gg = 0; gg < 8; ++gg) {
            const int col = bn + wn + (gg >> 1) * 16 + (gg & 1) * 8 + tig * 2;
            const float2 p0 = *reinterpret_cast<const float2*>(av0 + col);
            const float2 p1 = *reinterpret_cast<const float2*>(av1 + col);
            float v00 = acc[mt][gg][0] + p0.x, v01 = acc[mt][gg][1] + p0.y;
            float v10 = acc[mt][gg][2] + p1.x, v11 = acc[mt][gg][3] + p1.y;
            if (FUSE1) {
                v00 = fmaxf(v00, 0.f); v01 = fmaxf(v01, 0.f);
                v10 = fmaxf(v10, 0.f); v11 = fmaxf(v11, 0.f);
                __half2 h0 = __floats2half2_rn(v00, v01);
                __half2 h1 = __floats2half2_rn(v10, v11);
                *reinterpret_cast<__half2*>(g_hid + (size_t)r0 * HDIM + col) = h0;
                *reinterpret_cast<__half2*>(g_hid + (size_t)r1 * HDIM + col) = h1;
            } else {
                *reinterpret_cast<float2*>(out + (size_t)r0 * HDIM + col) = make_float2(v00, v01);
                *reinterpret_cast<float2*>(out + (size_t)r1 * HDIM + col) = make_float2(v10, v11);
            }
        }
    }
}

// ---------------------------------------------------------------- launch
extern "C" void kernel_launch(void* const* d_in, const int* in_sizes, int n_in,
                              void* d_out, int out_size) {
    (void)in_sizes; (void)n_in; (void)out_size;
    const float* features = (const float*)d_in[0];
    const float* protos   = (const float*)d_in[1];
    const float* W1       = (const float*)d_in[2];
    const float* b1       = (const float*)d_in[3];
    const float* W2       = (const float*)d_in[4];
    const float* b2       = (const float*)d_in[5];
    float* out = (float*)d_out;

    cudaFuncSetAttribute(f16_gemm_kernel<true>,  cudaFuncAttributeMaxDynamicSharedMemorySize, GSMEM);
    cudaFuncSetAttribute(f16_gemm_kernel<false>, cudaFuncAttributeMaxDynamicSharedMemorySize, GSMEM);

    pp_kernel<<<1, 320>>>(protos);
    argcvt_kernel<<<BATCH / 32, 256>>>(features, protos);
    tcvt_kernel<0><<<dim3(32, 32), dim3(32, 8)>>>(W1);
    tcvt_kernel<1><<<dim3(32, 32), dim3(32, 8)>>>(W2);
    protow1_kernel<<<dim3(HDIM / 256, NFAM), 256>>>(protos, W1, b1);

    dim3 grid(HDIM / 128, BATCH / 128);   // (8, 256)
    f16_gemm_kernel<true><<<grid, 256, GSMEM>>>(nullptr, nullptr);
    f16_gemm_kernel<false><<<grid, 256, GSMEM>>>(b2, out);
}